// round 14
// baseline (speedup 1.0000x reference)
#include <cuda_runtime.h>
#include <cuda_fp16.h>
#include <cstdint>
#include <cstddef>

// ---------------- problem constants ----------------
#define B_SZ   2048
#define I_SZ   256
#define P_SZ   257
#define FLATK  66049        // 257*257
#define N1     512

// ---------------- kernel-1 tiling (main part: i<256, j<256) ----------------
#define BM     128
#define BN     64
#define CSTR   264          // c_s row stride in halves
#define NSTR   72           // B tile n stride in halves
#define NKT    8            // j tiles per i (exact 256)
#define NIG_G  64           // i-groups per warp-group
#define BS_HALVES (64*NSTR)
#define SMEM_C_BYTES (BM*CSTR*2)          // 67584
#define SMEM_TOTAL   (SMEM_C_BYTES + 6*BS_HALVES*2)  // 122880

// ---------------- k2/border tiling ----------------
#define K2_ABUF  18432
#define K2_BBUF  9216
#define K2_BUF   (K2_ABUF + K2_BBUF)
#define K2_SMEM  (3 * K2_BUF)             // 82944

#define AB_K     576        // border K padded: 513 -> 9*64
#define NWORK    20         // worker CTAs (148 - 128)
#define CHUNK_R  514        // rows per conversion chunk (= one igl of one group)
#define CHUNK_E  (CHUNK_R * N1)   // 263168 elems

// statics
__device__ __half g_W1h[(size_t)FLATK * N1];
__device__ __half g_W2h[(size_t)N1 * N1];
__device__ __half g_Hh[(size_t)B_SZ * N1];
__device__ __half g_Ab[(size_t)B_SZ * AB_K];
__device__ float  g_Bord[(size_t)B_SZ * N1];
__device__ int    g_done[128];     // border tile flags
__device__ int    g_doneW[128];    // W-conversion chunk flags: [grp*64 + igl]

__device__ __forceinline__ void mma16(float* d, uint32_t a0, uint32_t a1,
                                      uint32_t a2, uint32_t a3,
                                      uint32_t b0, uint32_t b1) {
    asm volatile(
        "mma.sync.aligned.m16n8k16.row.col.f32.f16.f16.f32 "
        "{%0,%1,%2,%3}, {%4,%5,%6,%7}, {%8,%9}, {%0,%1,%2,%3};"
        : "+f"(d[0]), "+f"(d[1]), "+f"(d[2]), "+f"(d[3])
        : "r"(a0), "r"(a1), "r"(a2), "r"(a3), "r"(b0), "r"(b1));
}
__device__ __forceinline__ uint32_t smem_u32(const void* p) {
    uint32_t a;
    asm("{ .reg .u64 t; cvta.to.shared.u64 t, %1; cvt.u32.u64 %0, t; }" : "=r"(a) : "l"(p));
    return a;
}
__device__ __forceinline__ void ldm_x4(uint32_t& r0, uint32_t& r1, uint32_t& r2,
                                       uint32_t& r3, uint32_t a) {
    asm volatile("ldmatrix.sync.aligned.m8n8.x4.shared.b16 {%0,%1,%2,%3}, [%4];"
                 : "=r"(r0), "=r"(r1), "=r"(r2), "=r"(r3) : "r"(a));
}
__device__ __forceinline__ void ldm_x4t(uint32_t& r0, uint32_t& r1, uint32_t& r2,
                                        uint32_t& r3, uint32_t a) {
    asm volatile("ldmatrix.sync.aligned.m8n8.x4.trans.shared.b16 {%0,%1,%2,%3}, [%4];"
                 : "=r"(r0), "=r"(r1), "=r"(r2), "=r"(r3) : "r"(a));
}
__device__ __forceinline__ void cpa16(uint32_t s, const void* g) {
    asm volatile("cp.async.cg.shared.global [%0], [%1], 16;" :: "r"(s), "l"(g));
}
__device__ __forceinline__ void cpcommit() { asm volatile("cp.async.commit_group;"); }
__device__ __forceinline__ void cpwait1()  { asm volatile("cp.async.wait_group 1;"); }
__device__ __forceinline__ void cpwait0()  { asm volatile("cp.async.wait_group 0;"); }
__device__ __forceinline__ void bar_named(int id) {
    asm volatile("bar.sync %0, 256;" :: "r"(id) : "memory");
}
// release publish / acquire consume (gpu scope)
__device__ __forceinline__ void flag_set(int* p) {
    asm volatile("st.global.release.gpu.s32 [%0], 1;" :: "l"(p) : "memory");
}
__device__ __forceinline__ int flag_get(const int* p) {
    int v;
    asm volatile("ld.global.acquire.gpu.s32 %0, [%1];" : "=r"(v) : "l"(p) : "memory");
    return v;
}

// ---------------------------------------------------------------------------
// Prep kernel: convA + convW2 + flag reset, one launch (1152 blocks).
// ---------------------------------------------------------------------------
__global__ void __launch_bounds__(256)
prep_k(const float* __restrict__ inp1, const float* __restrict__ inp2,
       const float* __restrict__ W2)
{
    const int bid = blockIdx.x, tid = threadIdx.x;

    if (bid == 0) {
        if (tid < 128) g_done[tid] = 0;
        else           g_doneW[tid - 128] = 0;
    }

    if (bid < 128) {
        size_t idx = ((size_t)bid * 256 + tid) * 8;
        float4 v0 = *(const float4*)(W2 + idx);
        float4 v1 = *(const float4*)(W2 + idx + 4);
        __half2 h0 = __floats2half2_rn(v0.x, v0.y);
        __half2 h1 = __floats2half2_rn(v0.z, v0.w);
        __half2 h2 = __floats2half2_rn(v1.x, v1.y);
        __half2 h3 = __floats2half2_rn(v1.z, v1.w);
        uint4 u;
        u.x = *(uint32_t*)&h0; u.y = *(uint32_t*)&h1;
        u.z = *(uint32_t*)&h2; u.w = *(uint32_t*)&h3;
        *(uint4*)(g_W2h + idx) = u;
    }

    int t = bid * 256 + tid;
    int m = t / (AB_K / 4);
    int c4 = (t - m * (AB_K / 4)) * 4;
    __half h[4];
    #pragma unroll
    for (int e = 0; e < 4; ++e) {
        int col = c4 + e;
        float v;
        if (col < I_SZ)       v = inp2[(size_t)m * I_SZ + col];
        else if (col == I_SZ) v = 1.0f;
        else if (col < 513)   v = inp1[(size_t)m * I_SZ + (col - 257)];
        else                  v = 0.0f;
        h[e] = __float2half_rn(v);
    }
    uint2 u2;
    u2.x = *(uint32_t*)&h[0];
    u2.y = *(uint32_t*)&h[2];
    *(uint2*)&g_Ab[(size_t)m * AB_K + c4] = u2;
}

// ---------------------------------------------------------------------------
// Fused kernel 1: 148 CTAs, all wave-1 co-resident (smem forces 1 CTA/SM).
//   bid <  128 : main GEMM (i<256, j<256) — waits on per-igl W-chunk flags
//   bid >= 128 : worker — (a) convert its W1 region to fp16 in consumption
//                order, publishing g_doneW; (b) border GEMM with fp32-direct B.
// ---------------------------------------------------------------------------
extern __shared__ char smem1[];

__global__ void __launch_bounds__(512, 1)
fused_k1(const float* __restrict__ inp1, const float* __restrict__ inp2,
         const float* __restrict__ W1, const float* __restrict__ b1)
{
    const int bid  = blockIdx.x;
    const int tid  = threadIdx.x;
    const int lane = tid & 31;
    const int wid  = tid >> 5;
    const int gq   = lane >> 2;
    const int tig  = lane & 3;

    const int quad = lane >> 3, lrow = lane & 7;
    const int lmr  = (quad & 1) * 8 + lrow;
    const int lmc  = (quad >> 1) * 8;

    // =======================================================================
    // WORKER PATH
    // =======================================================================
    if (bid >= 128) {
        const int worker = bid - 128;

        // ---- phase 1: convert W1 region to fp16 (all 512 threads) ----
        {
            const int reg   = (worker >= 10) ? 1 : 0;
            const int wloc  = reg ? worker - 10 : worker;
            const size_t rbase = reg ? (size_t)32896 * N1 : 0;
            for (int c = wloc; c < 64; c += 10) {
                const size_t eb = rbase + (size_t)c * CHUNK_E;
                for (int idx = tid * 8; idx < CHUNK_E; idx += 512 * 8) {
                    const size_t e = eb + idx;
                    float4 v0 = *(const float4*)(W1 + e);
                    float4 v1 = *(const float4*)(W1 + e + 4);
                    __half2 h0 = __floats2half2_rn(v0.x, v0.y);
                    __half2 h1 = __floats2half2_rn(v0.z, v0.w);
                    __half2 h2 = __floats2half2_rn(v1.x, v1.y);
                    __half2 h3 = __floats2half2_rn(v1.z, v1.w);
                    uint4 u;
                    u.x = *(uint32_t*)&h0; u.y = *(uint32_t*)&h1;
                    u.z = *(uint32_t*)&h2; u.w = *(uint32_t*)&h3;
                    *(uint4*)(g_W1h + e) = u;
                }
                __syncthreads();
                if (tid == 0) flag_set(&g_doneW[reg * 64 + c]);
            }
        }

        // ---- phase 2: border GEMM (warps 0..7, 256 threads) ----
        if (wid >= 8) return;
        const int wm = wid & 3;
        const int wn = wid >> 2;
        const uint32_t sbase = smem_u32(smem1);
        const uint32_t abase = sbase;
        const uint32_t bbase = sbase + K2_ABUF;

        for (int t = worker; t < 128; t += NWORK) {
            const int n0 = (t & 7) * BN;
            const int m0 = (t >> 3) * BM;

            float acc[2][4][4];
            #pragma unroll
            for (int mt = 0; mt < 2; ++mt)
                #pragma unroll
                for (int nt = 0; nt < 4; ++nt)
                    #pragma unroll
                    for (int r = 0; r < 4; ++r) acc[mt][nt][r] = 0.0f;

            const int NST = AB_K / 64;   // 9
            for (int s = 0; s < NST; ++s) {
                bar_named(3);            // prior stage reads done

                const int k0 = s * 64;
                #pragma unroll
                for (int q = 0; q < 4; ++q) {
                    int ch  = tid + q * 256;
                    int row = ch >> 3;
                    int c16 = ch & 7;
                    const __half* src = g_Ab + (size_t)(m0 + row) * AB_K + k0 + c16 * 8;
                    cpa16(abase + (uint32_t)(row * 144 + c16 * 16), src);
                }
                cpcommit();

                // B tile: fp32 direct load + convert + STS
                {
                    int row = tid >> 2;
                    int cg  = (tid & 3) * 16;
                    int kk  = k0 + row;
                    int grow;
                    if (kk < 257)      grow = 65792 + kk;
                    else if (kk < 513) grow = (kk - 257) * P_SZ + 256;
                    else               grow = 0;
                    const float* wsrc = W1 + (size_t)grow * N1 + n0 + cg;
                    float4 f0 = *(const float4*)(wsrc);
                    float4 f1 = *(const float4*)(wsrc + 4);
                    float4 f2 = *(const float4*)(wsrc + 8);
                    float4 f3 = *(const float4*)(wsrc + 12);
                    __half2 h0 = __floats2half2_rn(f0.x, f0.y);
                    __half2 h1 = __floats2half2_rn(f0.z, f0.w);
                    __half2 h2 = __floats2half2_rn(f1.x, f1.y);
                    __half2 h3 = __floats2half2_rn(f1.z, f1.w);
                    __half2 h4 = __floats2half2_rn(f2.x, f2.y);
                    __half2 h5 = __floats2half2_rn(f2.z, f2.w);
                    __half2 h6 = __floats2half2_rn(f3.x, f3.y);
                    __half2 h7 = __floats2half2_rn(f3.z, f3.w);
                    uint4 ua, ub;
                    ua.x = *(uint32_t*)&h0; ua.y = *(uint32_t*)&h1;
                    ua.z = *(uint32_t*)&h2; ua.w = *(uint32_t*)&h3;
                    ub.x = *(uint32_t*)&h4; ub.y = *(uint32_t*)&h5;
                    ub.z = *(uint32_t*)&h6; ub.w = *(uint32_t*)&h7;
                    char* bs = smem1 + K2_ABUF;
                    *(uint4*)(bs + row * 144 + cg * 2)      = ua;
                    *(uint4*)(bs + row * 144 + cg * 2 + 16) = ub;
                }

                cpwait0();
                bar_named(3);            // A + B visible

                #pragma unroll
                for (int ks = 0; ks < 4; ++ks) {
                    uint32_t A[2][4];
                    #pragma unroll
                    for (int mt = 0; mt < 2; ++mt) {
                        uint32_t addr = abase + (uint32_t)(
                            (wm * 32 + mt * 16 + lmr) * 144 + (ks * 16 + lmc) * 2);
                        ldm_x4(A[mt][0], A[mt][1], A[mt][2], A[mt][3], addr);
                    }
                    #pragma unroll
                    for (int nh = 0; nh < 2; ++nh) {
                        uint32_t addr = bbase + (uint32_t)(
                            (ks * 16 + lmr) * 144 + (wn * 32 + nh * 16 + lmc) * 2);
                        uint32_t b0, b1r, b2r, b3;
                        ldm_x4t(b0, b1r, b2r, b3, addr);
                        #pragma unroll
                        for (int mt = 0; mt < 2; ++mt) {
                            mma16(acc[mt][nh * 2 + 0], A[mt][0], A[mt][1], A[mt][2], A[mt][3], b0, b1r);
                            mma16(acc[mt][nh * 2 + 1], A[mt][0], A[mt][1], A[mt][2], A[mt][3], b2r, b3);
                        }
                    }
                }
            }

            // epilogue: + b1, fp32 store to g_Bord
            #pragma unroll
            for (int mt = 0; mt < 2; ++mt)
                #pragma unroll
                for (int nt = 0; nt < 4; ++nt) {
                    int n_base = n0 + wn * 32 + nt * 8 + tig * 2;
                    float bv0 = b1[n_base], bv1 = b1[n_base + 1];
                    #pragma unroll
                    for (int h = 0; h < 2; ++h) {
                        int m = m0 + wm * 32 + mt * 16 + h * 8 + gq;
                        *(float2*)&g_Bord[(size_t)m * N1 + n_base] =
                            make_float2(acc[mt][nt][h * 2 + 0] + bv0,
                                        acc[mt][nt][h * 2 + 1] + bv1);
                    }
                }

            bar_named(3);                // all stores done CTA-wide
            if (tid == 0) flag_set(&g_done[t]);
            bar_named(3);
        }
        return;
    }

    // =======================================================================
    // MAIN PATH (128 CTAs)
    // =======================================================================
    const int grp  = wid >> 3;
    const int gtid = tid & 255;
    const int gwid = wid & 7;
    const int wm   = gwid & 3;
    const int wn   = gwid >> 2;
    const int n0   = (bid & 7) * BN;
    const int m0   = (bid >> 3) * BM;

    __half* c_s = (__half*)smem1;
    __half* b_s = (__half*)(smem1 + SMEM_C_BYTES);

    const int igbase = grp * NIG_G;
    const uint32_t c_base  = smem_u32(c_s);
    const uint32_t bring_u = smem_u32(b_s) + (uint32_t)(grp * 3 * BS_HALVES * 2);

    for (int idx = tid; idx < BM * 256; idx += 512) {
        int m = idx >> 8, j = idx & 255;
        c_s[m * CSTR + j] = __float2half_rn(inp2[(size_t)(m0 + m) * I_SZ + j]);
    }
    __syncthreads();

    auto issueW = [&](int igl, int kt, int buf) {
        int ig = igbase + igl;
        #pragma unroll
        for (int q = 0; q < 2; ++q) {
            int ch  = gtid + q * 256;
            int row = ch >> 3;
            int c16 = ch & 7;
            int i   = ig * 2 + (row >> 5);
            int grow = i * P_SZ + kt * 32 + (row & 31);
            const __half* src = g_W1h + (size_t)grow * N1 + n0 + c16 * 8;
            uint32_t dst = bring_u + (uint32_t)(buf * BS_HALVES * 2 + row * 144 + c16 * 16);
            cpa16(dst, src);
        }
    };

    auto waitF = [&](int c) {
        if (gtid == 0) {
            while (flag_get(&g_doneW[grp * 64 + c]) == 0) __nanosleep(32);
        }
        bar_named(grp + 1);
    };

    float h_acc[2][4][4];
    #pragma unroll
    for (int mt = 0; mt < 2; ++mt)
        #pragma unroll
        for (int nt = 0; nt < 4; ++nt)
            #pragma unroll
            for (int r = 0; r < 4; ++r) h_acc[mt][nt][r] = 0.0f;

    int lastF = 0;
    waitF(0);
    issueW(0, 0, 0); cpcommit();
    issueW(0, 1, 1); cpcommit();

    int bufR = 0, bufW = 2;

    for (int igl = 0; igl < NIG_G; ++igl) {
        float av[2][4];
        #pragma unroll
        for (int g = 0; g < 2; ++g) {
            int i = (igbase + igl) * 2 + g;
            #pragma unroll
            for (int q = 0; q < 4; ++q) {
                int m = m0 + wm * 32 + (q >> 1) * 16 + (q & 1) * 8 + gq;
                av[g][q] = __ldg(&inp1[(size_t)m * I_SZ + i]);
            }
        }

        float tmp[2][2][4][4];
        #pragma unroll
        for (int g = 0; g < 2; ++g)
            #pragma unroll
            for (int mt = 0; mt < 2; ++mt)
                #pragma unroll
                for (int nt = 0; nt < 4; ++nt)
                    #pragma unroll
                    for (int q = 0; q < 4; ++q) tmp[g][mt][nt][q] = 0.0f;

        for (int kt = 0; kt < NKT; ++kt) {
            const int j0 = kt * 32;
            uint32_t A[2][2][4];
            #pragma unroll
            for (int ks = 0; ks < 2; ++ks)
                #pragma unroll
                for (int mt = 0; mt < 2; ++mt) {
                    uint32_t addr = c_base + 2u * (uint32_t)(
                        (wm * 32 + mt * 16 + lmr) * CSTR + j0 + ks * 16 + lmc);
                    ldm_x4(A[ks][mt][0], A[ks][mt][1], A[ks][mt][2], A[ks][mt][3], addr);
                }

            cpwait1();
            bar_named(grp + 1);

            // MMAs first (critical path), prefetch after
            const uint32_t bb = bring_u + (uint32_t)(bufR * BS_HALVES * 2);
            #pragma unroll
            for (int g = 0; g < 2; ++g) {
                #pragma unroll
                for (int ks = 0; ks < 2; ++ks) {
                    #pragma unroll
                    for (int nh = 0; nh < 2; ++nh) {
                        uint32_t addr = bb + 2u * (uint32_t)(
                            (g * 32 + ks * 16 + lmr) * NSTR + wn * 32 + nh * 16 + lmc);
                        uint32_t b0, b1r, b2r, b3;
                        ldm_x4t(b0, b1r, b2r, b3, addr);
                        #pragma unroll
                        for (int mt = 0; mt < 2; ++mt) {
                            mma16(tmp[g][mt][nh * 2 + 0],
                                  A[ks][mt][0], A[ks][mt][1], A[ks][mt][2], A[ks][mt][3],
                                  b0, b1r);
                            mma16(tmp[g][mt][nh * 2 + 1],
                                  A[ks][mt][0], A[ks][mt][1], A[ks][mt][2], A[ks][mt][3],
                                  b2r, b3);
                        }
                    }
                }
            }

            int kt2 = kt + 2, ig2 = igl;
            if (kt2 >= NKT) { kt2 -= NKT; ++ig2; }
            if (ig2 < NIG_G) {
                if (ig2 > lastF) { waitF(ig2); lastF = ig2; }
                issueW(ig2, kt2, bufW);
            }
            cpcommit();

            bufR = (bufR == 2) ? 0 : bufR + 1;
            bufW = (bufW == 2) ? 0 : bufW + 1;
        }

        #pragma unroll
        for (int g = 0; g < 2; ++g)
            #pragma unroll
            for (int mt = 0; mt < 2; ++mt)
                #pragma unroll
                for (int nt = 0; nt < 4; ++nt)
                    #pragma unroll
                    for (int q = 0; q < 4; ++q)
                        h_acc[mt][nt][q] += av[g][mt * 2 + (q >> 1)] * tmp[g][mt][nt][q];
    }

    // ---- wait for this tile's border partial (producers co-resident) ----
    if (tid == 0) {
        while (flag_get(&g_done[bid]) == 0) { __nanosleep(64); }
    }
    __syncthreads();

    // ---- cross-group reduce through retired c_s region ----
    float* xbuf = (float*)smem1;
    if (grp == 1) {
        #pragma unroll
        for (int mt = 0; mt < 2; ++mt)
            #pragma unroll
            for (int nt = 0; nt < 4; ++nt)
                *(float4*)&xbuf[gtid * 36 + (mt * 4 + nt) * 4] =
                    make_float4(h_acc[mt][nt][0], h_acc[mt][nt][1],
                                h_acc[mt][nt][2], h_acc[mt][nt][3]);
    }
    __syncthreads();
    if (grp == 0) {
        #pragma unroll
        for (int mt = 0; mt < 2; ++mt)
            #pragma unroll
            for (int nt = 0; nt < 4; ++nt) {
                float4 p = *(const float4*)&xbuf[gtid * 36 + (mt * 4 + nt) * 4];
                h_acc[mt][nt][0] += p.x; h_acc[mt][nt][1] += p.y;
                h_acc[mt][nt][2] += p.z; h_acc[mt][nt][3] += p.w;

                int n_base = n0 + wn * 32 + nt * 8 + tig * 2;
                #pragma unroll
                for (int h = 0; h < 2; ++h) {
                    int m = m0 + wm * 32 + mt * 16 + h * 8 + gq;
                    const float2* bp = (const float2*)&g_Bord[(size_t)m * N1 + n_base];
                    float2 bo;
                    bo.x = __ldcg(&bp->x);
                    bo.y = __ldcg(&bp->y);
                    float v0 = fmaxf(h_acc[mt][nt][h * 2 + 0] + bo.x, 0.0f);
                    float v1 = fmaxf(h_acc[mt][nt][h * 2 + 1] + bo.y, 0.0f);
                    __half2 hv = __floats2half2_rn(v0, v1);
                    *(__half2*)&g_Hh[(size_t)m * N1 + n_base] = hv;
                }
            }
    }
}

// ---------------------------------------------------------------------------
// Kernel 2: out = relu( H @ W2 + b2 ) — fp16 tensor-core, fp32 accum.
// ---------------------------------------------------------------------------
extern __shared__ char smem2[];

__global__ void __launch_bounds__(256, 1)
fused_k2(const float* __restrict__ b2, float* __restrict__ out)
{
    const int tid  = threadIdx.x;
    const int lane = tid & 31;
    const int wid  = tid >> 5;
    const int wm   = wid & 3;
    const int wn   = wid >> 2;
    const int gq   = lane >> 2;
    const int tig  = lane & 3;
    const int m0   = blockIdx.y * BM;
    const int n0   = blockIdx.x * BN;

    const uint32_t sbase = smem_u32(smem2);
    const int quad = lane >> 3, lrow = lane & 7;
    const int lmr  = (quad & 1) * 8 + lrow;
    const int lmc  = (quad >> 1) * 8;

    auto issue = [&](int s, int buf) {
        const int k0 = s * 64;
        const uint32_t abase = sbase + (uint32_t)(buf * K2_BUF);
        #pragma unroll
        for (int q = 0; q < 4; ++q) {
            int ch  = tid + q * 256;
            int row = ch >> 3;
            int c16 = ch & 7;
            const __half* src = g_Hh + (size_t)(m0 + row) * N1 + k0 + c16 * 8;
            cpa16(abase + (uint32_t)(row * 144 + c16 * 16), src);
        }
        const uint32_t bbase = abase + K2_ABUF;
        #pragma unroll
        for (int q = 0; q < 2; ++q) {
            int ch  = tid + q * 256;
            int row = ch >> 3;
            int c16 = ch & 7;
            const __half* src = g_W2h + (size_t)(k0 + row) * N1 + n0 + c16 * 8;
            cpa16(bbase + (uint32_t)(row * 144 + c16 * 16), src);
        }
    };

    float acc[2][4][4];
    #pragma unroll
    for (int mt = 0; mt < 2; ++mt)
        #pragma unroll
        for (int nt = 0; nt < 4; ++nt)
            #pragma unroll
            for (int r = 0; r < 4; ++r) acc[mt][nt][r] = 0.0f;

    issue(0, 0); cpcommit();
    issue(1, 1); cpcommit();

    int bufR = 0, bufW = 2;
    const int NST = N1 / 64;

    for (int s = 0; s < NST; ++s) {
        cpwait1();
        __syncthreads();
        if (s + 2 < NST) issue(s + 2, bufW);
        cpcommit();

        const uint32_t abase = sbase + (uint32_t)(bufR * K2_BUF);
        const uint32_t bbase = abase + K2_ABUF;

        #pragma unroll
        for (int ks = 0; ks < 4; ++ks) {
            uint32_t A[2][4];
            #pragma unroll
            for (int mt = 0; mt < 2; ++mt) {
                uint32_t addr = abase + (uint32_t)(
                    (wm * 32 + mt * 16 + lmr) * 144 + (ks * 16 + lmc) * 2);
                ldm_x4(A[mt][0], A[mt][1], A[mt][2], A[mt][3], addr);
            }
            #pragma unroll
            for (int nh = 0; nh < 2; ++nh) {
                uint32_t addr = bbase + (uint32_t)(
                    (ks * 16 + lmr) * 144 + (wn * 32 + nh * 16 + lmc) * 2);
                uint32_t b0, b1, b2, b3;
                ldm_x4t(b0, b1, b2, b3, addr);
                #pragma unroll
                for (int mt = 0; mt < 2; ++mt) {
                    mma16(acc[mt][nh * 2 + 0], A[mt][0], A[mt][1], A[mt][2], A[mt][3], b0, b1);
                    mma16(acc[mt][nh * 2 + 1], A[mt][0], A[mt][1], A[mt][2], A[mt][3], b2, b3);
                }
            }
        }
        bufR = (bufR == 2) ? 0 : bufR + 1;
        bufW = (bufW == 2) ? 0 : bufW + 1;
    }

    #pragma unroll
    for (int mt = 0; mt < 2; ++mt)
        #pragma unroll
        for (int nt = 0; nt < 4; ++nt) {
            int n_base = n0 + wn * 32 + nt * 8 + tig * 2;
            float bv0 = b2[n_base], bv1 = b2[n_base + 1];
            #pragma unroll
            for (int h = 0; h < 2; ++h) {
                int m = m0 + wm * 32 + mt * 16 + h * 8 + gq;
                float v0 = fmaxf(acc[mt][nt][h * 2 + 0] + bv0, 0.0f);
                float v1 = fmaxf(acc[mt][nt][h * 2 + 1] + bv1, 0.0f);
                *(float2*)&out[(size_t)m * N1 + n_base] = make_float2(v0, v1);
            }
        }
}

// ---------------------------------------------------------------------------
extern "C" void kernel_launch(void* const* d_in, const int* in_sizes, int n_in,
                              void* d_out, int out_size)
{
    const float* inp1 = (const float*)d_in[0];
    const float* inp2 = (const float*)d_in[1];
    const float* W1   = (const float*)d_in[2];
    const float* b1   = (const float*)d_in[3];
    const float* W2   = (const float*)d_in[4];
    const float* b2   = (const float*)d_in[5];
    (void)in_sizes; (void)n_in; (void)out_size;

    prep_k<<<(B_SZ * (AB_K / 4)) / 256, 256>>>(inp1, inp2, W2);   // 1152 blocks

    cudaFuncSetAttribute(fused_k1, cudaFuncAttributeMaxDynamicSharedMemorySize, SMEM_TOTAL);
    fused_k1<<<148, 512, SMEM_TOTAL>>>(inp1, inp2, W1, b1);

    cudaFuncSetAttribute(fused_k2, cudaFuncAttributeMaxDynamicSharedMemorySize, K2_SMEM);
    fused_k2<<<dim3(N1 / BN, B_SZ / BM), 256, K2_SMEM>>>(b2, (float*)d_out);
}

// round 15
// speedup vs baseline: 1.0485x; 1.0485x over previous
#include <cuda_runtime.h>
#include <cuda_fp16.h>
#include <cstdint>
#include <cstddef>

// ---------------- problem constants ----------------
#define B_SZ   2048
#define I_SZ   256
#define P_SZ   257
#define FLATK  66049        // 257*257
#define N1     512

// ---------------- kernel-1 tiling (main part: i<256, j<256) ----------------
#define BM     128
#define BN     64
#define CSTR   264          // c_s row stride in halves
#define NSTR   72           // B tile n stride in halves
#define NKT    8            // j tiles per i (exact 256)
#define NIG_G  64           // i-groups per warp-group
#define BS_HALVES (64*NSTR)
#define SMEM_C_BYTES (BM*CSTR*2)          // 67584
#define SMEM_TOTAL   (SMEM_C_BYTES + 6*BS_HALVES*2)  // 122880

// ---------------- k2/border tiling ----------------
#define K2_ABUF  18432
#define K2_BBUF  9216
#define K2_BUF   (K2_ABUF + K2_BBUF)
#define K2_SMEM  (3 * K2_BUF)             // 82944

#define AB_K     576        // border K padded: 513 -> 9*64
#define NWORK    20         // border worker CTAs (148 - 128)

// prep_all block partition
#define NB_W1   16513       // ceil(66049*512 / 2048)
#define NB_W2   128         // 512*512 / 2048
#define NB_A    1152        // 2048*144 / 256
#define NB_ALL  (NB_W1 + NB_W2 + NB_A)    // 17793

// statics
__device__ __half g_W1h[(size_t)FLATK * N1];
__device__ __half g_W2h[(size_t)N1 * N1];
__device__ __half g_Hh[(size_t)B_SZ * N1];
__device__ __half g_Ab[(size_t)B_SZ * AB_K];
__device__ float  g_Bord[(size_t)B_SZ * N1];
__device__ int    g_done[128];     // border tile flags

__device__ __forceinline__ void mma16(float* d, uint32_t a0, uint32_t a1,
                                      uint32_t a2, uint32_t a3,
                                      uint32_t b0, uint32_t b1) {
    asm volatile(
        "mma.sync.aligned.m16n8k16.row.col.f32.f16.f16.f32 "
        "{%0,%1,%2,%3}, {%4,%5,%6,%7}, {%8,%9}, {%0,%1,%2,%3};"
        : "+f"(d[0]), "+f"(d[1]), "+f"(d[2]), "+f"(d[3])
        : "r"(a0), "r"(a1), "r"(a2), "r"(a3), "r"(b0), "r"(b1));
}
__device__ __forceinline__ uint32_t smem_u32(const void* p) {
    uint32_t a;
    asm("{ .reg .u64 t; cvta.to.shared.u64 t, %1; cvt.u32.u64 %0, t; }" : "=r"(a) : "l"(p));
    return a;
}
__device__ __forceinline__ void ldm_x4(uint32_t& r0, uint32_t& r1, uint32_t& r2,
                                       uint32_t& r3, uint32_t a) {
    asm volatile("ldmatrix.sync.aligned.m8n8.x4.shared.b16 {%0,%1,%2,%3}, [%4];"
                 : "=r"(r0), "=r"(r1), "=r"(r2), "=r"(r3) : "r"(a));
}
__device__ __forceinline__ void ldm_x4t(uint32_t& r0, uint32_t& r1, uint32_t& r2,
                                        uint32_t& r3, uint32_t a) {
    asm volatile("ldmatrix.sync.aligned.m8n8.x4.trans.shared.b16 {%0,%1,%2,%3}, [%4];"
                 : "=r"(r0), "=r"(r1), "=r"(r2), "=r"(r3) : "r"(a));
}
__device__ __forceinline__ void cpa16(uint32_t s, const void* g) {
    asm volatile("cp.async.cg.shared.global [%0], [%1], 16;" :: "r"(s), "l"(g));
}
__device__ __forceinline__ void cpcommit() { asm volatile("cp.async.commit_group;"); }
__device__ __forceinline__ void cpwait1()  { asm volatile("cp.async.wait_group 1;"); }
__device__ __forceinline__ void cpwait0()  { asm volatile("cp.async.wait_group 0;"); }
__device__ __forceinline__ void bar_named(int id) {
    asm volatile("bar.sync %0, 256;" :: "r"(id) : "memory");
}
// release publish / acquire consume (gpu scope)
__device__ __forceinline__ void flag_set(int* p) {
    asm volatile("st.global.release.gpu.s32 [%0], 1;" :: "l"(p) : "memory");
}
__device__ __forceinline__ int flag_get(const int* p) {
    int v;
    asm volatile("ld.global.acquire.gpu.s32 %0, [%1];" : "=r"(v) : "l"(p) : "memory");
    return v;
}

__device__ __forceinline__ uint4 cvt8_f32_to_h16(float4 v0, float4 v1) {
    __half2 h0 = __floats2half2_rn(v0.x, v0.y);
    __half2 h1 = __floats2half2_rn(v0.z, v0.w);
    __half2 h2 = __floats2half2_rn(v1.x, v1.y);
    __half2 h3 = __floats2half2_rn(v1.z, v1.w);
    uint4 u;
    u.x = *(uint32_t*)&h0; u.y = *(uint32_t*)&h1;
    u.z = *(uint32_t*)&h2; u.w = *(uint32_t*)&h3;
    return u;
}

// ---------------------------------------------------------------------------
// prep_all: convW1 + convW2 + convA + flag reset in ONE launch.
//   bid <  NB_W1              : W1 -> fp16 (8 elems/thread, guarded tail)
//   bid in [NB_W1, +NB_W2)    : W2 -> fp16
//   bid in [NB_W1+NB_W2, end) : g_Ab = [cext | a | 0pad] fp16
//   bid == 0, tid < 128       : g_done reset
// ---------------------------------------------------------------------------
__global__ void __launch_bounds__(256)
prep_all(const float* __restrict__ inp1, const float* __restrict__ inp2,
         const float* __restrict__ W1, const float* __restrict__ W2)
{
    const int bid = blockIdx.x, tid = threadIdx.x;

    if (bid == 0 && tid < 128) g_done[tid] = 0;

    if (bid < NB_W1) {
        const size_t total = (size_t)FLATK * N1;
        size_t idx = ((size_t)bid * 256 + tid) * 8;
        if (idx >= total) return;
        float4 v0 = *(const float4*)(W1 + idx);
        float4 v1 = *(const float4*)(W1 + idx + 4);
        *(uint4*)(g_W1h + idx) = cvt8_f32_to_h16(v0, v1);
        return;
    }

    if (bid < NB_W1 + NB_W2) {
        size_t idx = ((size_t)(bid - NB_W1) * 256 + tid) * 8;
        float4 v0 = *(const float4*)(W2 + idx);
        float4 v1 = *(const float4*)(W2 + idx + 4);
        *(uint4*)(g_W2h + idx) = cvt8_f32_to_h16(v0, v1);
        return;
    }

    // convA
    int t = (bid - NB_W1 - NB_W2) * 256 + tid;
    int m = t / (AB_K / 4);
    int c4 = (t - m * (AB_K / 4)) * 4;
    __half h[4];
    #pragma unroll
    for (int e = 0; e < 4; ++e) {
        int col = c4 + e;
        float v;
        if (col < I_SZ)       v = inp2[(size_t)m * I_SZ + col];
        else if (col == I_SZ) v = 1.0f;
        else if (col < 513)   v = inp1[(size_t)m * I_SZ + (col - 257)];
        else                  v = 0.0f;
        h[e] = __float2half_rn(v);
    }
    uint2 u2;
    u2.x = *(uint32_t*)&h[0];
    u2.y = *(uint32_t*)&h[2];
    *(uint2*)&g_Ab[(size_t)m * AB_K + c4] = u2;
}

// ---------------------------------------------------------------------------
// Fused kernel 1: 148 CTAs, all wave-1 co-resident (smem forces 1 CTA/SM).
//   bid <  128 : main GEMM (i<256, j<256), 512 thr, 2 warp-groups
//   bid >= 128 : border worker — g_Bord = [cext|a] @ Wb + b1, per-tile flags.
// ---------------------------------------------------------------------------
extern __shared__ char smem1[];

__global__ void __launch_bounds__(512, 1)
fused_k1(const float* __restrict__ inp1, const float* __restrict__ inp2,
         const float* __restrict__ b1)
{
    const int bid  = blockIdx.x;
    const int tid  = threadIdx.x;
    const int lane = tid & 31;
    const int wid  = tid >> 5;
    const int gq   = lane >> 2;
    const int tig  = lane & 3;

    const int quad = lane >> 3, lrow = lane & 7;
    const int lmr  = (quad & 1) * 8 + lrow;
    const int lmc  = (quad >> 1) * 8;

    // =======================================================================
    // BORDER WORKER PATH
    // =======================================================================
    if (bid >= 128) {
        if (wid >= 8) return;          // warps 0..7 only (256 threads)
        const int worker = bid - 128;
        const int wm = wid & 3;
        const int wn = wid >> 2;
        const uint32_t sbase = smem_u32(smem1);

        for (int t = worker; t < 128; t += NWORK) {
            const int n0 = (t & 7) * BN;
            const int m0 = (t >> 3) * BM;

            auto issue = [&](int s, int buf) {
                const int k0 = s * 64;
                const uint32_t abase = sbase + (uint32_t)(buf * K2_BUF);
                #pragma unroll
                for (int q = 0; q < 4; ++q) {
                    int ch  = tid + q * 256;
                    int row = ch >> 3;
                    int c16 = ch & 7;
                    const __half* src = g_Ab + (size_t)(m0 + row) * AB_K + k0 + c16 * 8;
                    cpa16(abase + (uint32_t)(row * 144 + c16 * 16), src);
                }
                const uint32_t bbase = abase + K2_ABUF;
                #pragma unroll
                for (int q = 0; q < 2; ++q) {
                    int ch  = tid + q * 256;
                    int row = ch >> 3;
                    int c16 = ch & 7;
                    int kk  = k0 + row;
                    int grow;
                    if (kk < 257)      grow = 65792 + kk;
                    else if (kk < 513) grow = (kk - 257) * P_SZ + 256;
                    else               grow = 0;
                    const __half* src = g_W1h + (size_t)grow * N1 + n0 + c16 * 8;
                    cpa16(bbase + (uint32_t)(row * 144 + c16 * 16), src);
                }
            };

            float acc[2][4][4];
            #pragma unroll
            for (int mt = 0; mt < 2; ++mt)
                #pragma unroll
                for (int nt = 0; nt < 4; ++nt)
                    #pragma unroll
                    for (int r = 0; r < 4; ++r) acc[mt][nt][r] = 0.0f;

            issue(0, 0); cpcommit();
            issue(1, 1); cpcommit();

            int bufR = 0, bufW = 2;
            const int NST = AB_K / 64;   // 9

            for (int s = 0; s < NST; ++s) {
                cpwait1();
                bar_named(3);
                if (s + 2 < NST) issue(s + 2, bufW);
                cpcommit();

                const uint32_t abase = sbase + (uint32_t)(bufR * K2_BUF);
                const uint32_t bbase = abase + K2_ABUF;

                #pragma unroll
                for (int ks = 0; ks < 4; ++ks) {
                    uint32_t A[2][4];
                    #pragma unroll
                    for (int mt = 0; mt < 2; ++mt) {
                        uint32_t addr = abase + (uint32_t)(
                            (wm * 32 + mt * 16 + lmr) * 144 + (ks * 16 + lmc) * 2);
                        ldm_x4(A[mt][0], A[mt][1], A[mt][2], A[mt][3], addr);
                    }
                    #pragma unroll
                    for (int nh = 0; nh < 2; ++nh) {
                        uint32_t addr = bbase + (uint32_t)(
                            (ks * 16 + lmr) * 144 + (wn * 32 + nh * 16 + lmc) * 2);
                        uint32_t b0, b1r, b2r, b3;
                        ldm_x4t(b0, b1r, b2r, b3, addr);
                        #pragma unroll
                        for (int mt = 0; mt < 2; ++mt) {
                            mma16(acc[mt][nh * 2 + 0], A[mt][0], A[mt][1], A[mt][2], A[mt][3], b0, b1r);
                            mma16(acc[mt][nh * 2 + 1], A[mt][0], A[mt][1], A[mt][2], A[mt][3], b2r, b3);
                        }
                    }
                }
                bufR = (bufR == 2) ? 0 : bufR + 1;
                bufW = (bufW == 2) ? 0 : bufW + 1;
            }

            // epilogue: + b1, fp32 store to g_Bord
            #pragma unroll
            for (int mt = 0; mt < 2; ++mt)
                #pragma unroll
                for (int nt = 0; nt < 4; ++nt) {
                    int n_base = n0 + wn * 32 + nt * 8 + tig * 2;
                    float bv0 = b1[n_base], bv1 = b1[n_base + 1];
                    #pragma unroll
                    for (int h = 0; h < 2; ++h) {
                        int m = m0 + wm * 32 + mt * 16 + h * 8 + gq;
                        *(float2*)&g_Bord[(size_t)m * N1 + n_base] =
                            make_float2(acc[mt][nt][h * 2 + 0] + bv0,
                                        acc[mt][nt][h * 2 + 1] + bv1);
                    }
                }

            bar_named(3);                // all stores done CTA-wide
            if (tid == 0) flag_set(&g_done[t]);
            bar_named(3);
        }
        return;
    }

    // =======================================================================
    // MAIN PATH (128 CTAs)
    // =======================================================================
    const int grp  = wid >> 3;
    const int gtid = tid & 255;
    const int gwid = wid & 7;
    const int wm   = gwid & 3;
    const int wn   = gwid >> 2;
    const int n0   = (bid & 7) * BN;
    const int m0   = (bid >> 3) * BM;

    __half* c_s = (__half*)smem1;
    __half* b_s = (__half*)(smem1 + SMEM_C_BYTES);

    const int igbase = grp * NIG_G;
    const uint32_t c_base  = smem_u32(c_s);
    const uint32_t bring_u = smem_u32(b_s) + (uint32_t)(grp * 3 * BS_HALVES * 2);

    for (int idx = tid; idx < BM * 256; idx += 512) {
        int m = idx >> 8, j = idx & 255;
        c_s[m * CSTR + j] = __float2half_rn(inp2[(size_t)(m0 + m) * I_SZ + j]);
    }
    __syncthreads();

    auto issueW = [&](int igl, int kt, int buf) {
        int ig = igbase + igl;
        #pragma unroll
        for (int q = 0; q < 2; ++q) {
            int ch  = gtid + q * 256;
            int row = ch >> 3;
            int c16 = ch & 7;
            int i   = ig * 2 + (row >> 5);
            int grow = i * P_SZ + kt * 32 + (row & 31);
            const __half* src = g_W1h + (size_t)grow * N1 + n0 + c16 * 8;
            uint32_t dst = bring_u + (uint32_t)(buf * BS_HALVES * 2 + row * 144 + c16 * 16);
            cpa16(dst, src);
        }
    };

    float h_acc[2][4][4];
    #pragma unroll
    for (int mt = 0; mt < 2; ++mt)
        #pragma unroll
        for (int nt = 0; nt < 4; ++nt)
            #pragma unroll
            for (int r = 0; r < 4; ++r) h_acc[mt][nt][r] = 0.0f;

    issueW(0, 0, 0); cpcommit();
    issueW(0, 1, 1); cpcommit();

    int bufR = 0, bufW = 2;

    for (int igl = 0; igl < NIG_G; ++igl) {
        float av[2][4];
        #pragma unroll
        for (int g = 0; g < 2; ++g) {
            int i = (igbase + igl) * 2 + g;
            #pragma unroll
            for (int q = 0; q < 4; ++q) {
                int m = m0 + wm * 32 + (q >> 1) * 16 + (q & 1) * 8 + gq;
                av[g][q] = __ldg(&inp1[(size_t)m * I_SZ + i]);
            }
        }

        float tmp[2][2][4][4];
        #pragma unroll
        for (int g = 0; g < 2; ++g)
            #pragma unroll
            for (int mt = 0; mt < 2; ++mt)
                #pragma unroll
                for (int nt = 0; nt < 4; ++nt)
                    #pragma unroll
                    for (int q = 0; q < 4; ++q) tmp[g][mt][nt][q] = 0.0f;

        for (int kt = 0; kt < NKT; ++kt) {
            const int j0 = kt * 32;
            uint32_t A[2][2][4];
            #pragma unroll
            for (int ks = 0; ks < 2; ++ks)
                #pragma unroll
                for (int mt = 0; mt < 2; ++mt) {
                    uint32_t addr = c_base + 2u * (uint32_t)(
                        (wm * 32 + mt * 16 + lmr) * CSTR + j0 + ks * 16 + lmc);
                    ldm_x4(A[ks][mt][0], A[ks][mt][1], A[ks][mt][2], A[ks][mt][3], addr);
                }

            cpwait1();
            bar_named(grp + 1);

            // MMAs first (critical path), prefetch after
            const uint32_t bb = bring_u + (uint32_t)(bufR * BS_HALVES * 2);
            #pragma unroll
            for (int g = 0; g < 2; ++g) {
                #pragma unroll
                for (int ks = 0; ks < 2; ++ks) {
                    #pragma unroll
                    for (int nh = 0; nh < 2; ++nh) {
                        uint32_t addr = bb + 2u * (uint32_t)(
                            (g * 32 + ks * 16 + lmr) * NSTR + wn * 32 + nh * 16 + lmc);
                        uint32_t b0, b1r, b2r, b3;
                        ldm_x4t(b0, b1r, b2r, b3, addr);
                        #pragma unroll
                        for (int mt = 0; mt < 2; ++mt) {
                            mma16(tmp[g][mt][nh * 2 + 0],
                                  A[ks][mt][0], A[ks][mt][1], A[ks][mt][2], A[ks][mt][3],
                                  b0, b1r);
                            mma16(tmp[g][mt][nh * 2 + 1],
                                  A[ks][mt][0], A[ks][mt][1], A[ks][mt][2], A[ks][mt][3],
                                  b2r, b3);
                        }
                    }
                }
            }

            int kt2 = kt + 2, ig2 = igl;
            if (kt2 >= NKT) { kt2 -= NKT; ++ig2; }
            if (ig2 < NIG_G) issueW(ig2, kt2, bufW);
            cpcommit();

            bufR = (bufR == 2) ? 0 : bufR + 1;
            bufW = (bufW == 2) ? 0 : bufW + 1;
        }

        #pragma unroll
        for (int g = 0; g < 2; ++g)
            #pragma unroll
            for (int mt = 0; mt < 2; ++mt)
                #pragma unroll
                for (int nt = 0; nt < 4; ++nt)
                    #pragma unroll
                    for (int q = 0; q < 4; ++q)
                        h_acc[mt][nt][q] += av[g][mt * 2 + (q >> 1)] * tmp[g][mt][nt][q];
    }

    // ---- wait for this tile's border partial (producers co-resident) ----
    if (tid == 0) {
        while (flag_get(&g_done[bid]) == 0) { __nanosleep(64); }
    }
    __syncthreads();

    // ---- cross-group reduce through retired c_s region ----
    float* xbuf = (float*)smem1;
    if (grp == 1) {
        #pragma unroll
        for (int mt = 0; mt < 2; ++mt)
            #pragma unroll
            for (int nt = 0; nt < 4; ++nt)
                *(float4*)&xbuf[gtid * 36 + (mt * 4 + nt) * 4] =
                    make_float4(h_acc[mt][nt][0], h_acc[mt][nt][1],
                                h_acc[mt][nt][2], h_acc[mt][nt][3]);
    }
    __syncthreads();
    if (grp == 0) {
        #pragma unroll
        for (int mt = 0; mt < 2; ++mt)
            #pragma unroll
            for (int nt = 0; nt < 4; ++nt) {
                float4 p = *(const float4*)&xbuf[gtid * 36 + (mt * 4 + nt) * 4];
                h_acc[mt][nt][0] += p.x; h_acc[mt][nt][1] += p.y;
                h_acc[mt][nt][2] += p.z; h_acc[mt][nt][3] += p.w;

                int n_base = n0 + wn * 32 + nt * 8 + tig * 2;
                #pragma unroll
                for (int h = 0; h < 2; ++h) {
                    int m = m0 + wm * 32 + mt * 16 + h * 8 + gq;
                    const float2* bp = (const float2*)&g_Bord[(size_t)m * N1 + n_base];
                    float2 bo;
                    bo.x = __ldcg(&bp->x);
                    bo.y = __ldcg(&bp->y);
                    float v0 = fmaxf(h_acc[mt][nt][h * 2 + 0] + bo.x, 0.0f);
                    float v1 = fmaxf(h_acc[mt][nt][h * 2 + 1] + bo.y, 0.0f);
                    __half2 hv = __floats2half2_rn(v0, v1);
                    *(__half2*)&g_Hh[(size_t)m * N1 + n_base] = hv;
                }
            }
    }
}

// ---------------------------------------------------------------------------
// Kernel 2: out = relu( H @ W2 + b2 ) — fp16 tensor-core, fp32 accum.
// ---------------------------------------------------------------------------
extern __shared__ char smem2[];

__global__ void __launch_bounds__(256, 1)
fused_k2(const float* __restrict__ b2, float* __restrict__ out)
{
    const int tid  = threadIdx.x;
    const int lane = tid & 31;
    const int wid  = tid >> 5;
    const int wm   = wid & 3;
    const int wn   = wid >> 2;
    const int gq   = lane >> 2;
    const int tig  = lane & 3;
    const int m0   = blockIdx.y * BM;
    const int n0   = blockIdx.x * BN;

    const uint32_t sbase = smem_u32(smem2);
    const int quad = lane >> 3, lrow = lane & 7;
    const int lmr  = (quad & 1) * 8 + lrow;
    const int lmc  = (quad >> 1) * 8;

    auto issue = [&](int s, int buf) {
        const int k0 = s * 64;
        const uint32_t abase = sbase + (uint32_t)(buf * K2_BUF);
        #pragma unroll
        for (int q = 0; q < 4; ++q) {
            int ch  = tid + q * 256;
            int row = ch >> 3;
            int c16 = ch & 7;
            const __half* src = g_Hh + (size_t)(m0 + row) * N1 + k0 + c16 * 8;
            cpa16(abase + (uint32_t)(row * 144 + c16 * 16), src);
        }
        const uint32_t bbase = abase + K2_ABUF;
        #pragma unroll
        for (int q = 0; q < 2; ++q) {
            int ch  = tid + q * 256;
            int row = ch >> 3;
            int c16 = ch & 7;
            const __half* src = g_W2h + (size_t)(k0 + row) * N1 + n0 + c16 * 8;
            cpa16(bbase + (uint32_t)(row * 144 + c16 * 16), src);
        }
    };

    float acc[2][4][4];
    #pragma unroll
    for (int mt = 0; mt < 2; ++mt)
        #pragma unroll
        for (int nt = 0; nt < 4; ++nt)
            #pragma unroll
            for (int r = 0; r < 4; ++r) acc[mt][nt][r] = 0.0f;

    issue(0, 0); cpcommit();
    issue(1, 1); cpcommit();

    int bufR = 0, bufW = 2;
    const int NST = N1 / 64;

    for (int s = 0; s < NST; ++s) {
        cpwait1();
        __syncthreads();
        if (s + 2 < NST) issue(s + 2, bufW);
        cpcommit();

        const uint32_t abase = sbase + (uint32_t)(bufR * K2_BUF);
        const uint32_t bbase = abase + K2_ABUF;

        #pragma unroll
        for (int ks = 0; ks < 4; ++ks) {
            uint32_t A[2][4];
            #pragma unroll
            for (int mt = 0; mt < 2; ++mt) {
                uint32_t addr = abase + (uint32_t)(
                    (wm * 32 + mt * 16 + lmr) * 144 + (ks * 16 + lmc) * 2);
                ldm_x4(A[mt][0], A[mt][1], A[mt][2], A[mt][3], addr);
            }
            #pragma unroll
            for (int nh = 0; nh < 2; ++nh) {
                uint32_t addr = bbase + (uint32_t)(
                    (ks * 16 + lmr) * 144 + (wn * 32 + nh * 16 + lmc) * 2);
                uint32_t b0, b1, b2, b3;
                ldm_x4t(b0, b1, b2, b3, addr);
                #pragma unroll
                for (int mt = 0; mt < 2; ++mt) {
                    mma16(acc[mt][nh * 2 + 0], A[mt][0], A[mt][1], A[mt][2], A[mt][3], b0, b1);
                    mma16(acc[mt][nh * 2 + 1], A[mt][0], A[mt][1], A[mt][2], A[mt][3], b2, b3);
                }
            }
        }
        bufR = (bufR == 2) ? 0 : bufR + 1;
        bufW = (bufW == 2) ? 0 : bufW + 1;
    }

    #pragma unroll
    for (int mt = 0; mt < 2; ++mt)
        #pragma unroll
        for (int nt = 0; nt < 4; ++nt) {
            int n_base = n0 + wn * 32 + nt * 8 + tig * 2;
            float bv0 = b2[n_base], bv1 = b2[n_base + 1];
            #pragma unroll
            for (int h = 0; h < 2; ++h) {
                int m = m0 + wm * 32 + mt * 16 + h * 8 + gq;
                float v0 = fmaxf(acc[mt][nt][h * 2 + 0] + bv0, 0.0f);
                float v1 = fmaxf(acc[mt][nt][h * 2 + 1] + bv1, 0.0f);
                *(float2*)&out[(size_t)m * N1 + n_base] = make_float2(v0, v1);
            }
        }
}

// ---------------------------------------------------------------------------
extern "C" void kernel_launch(void* const* d_in, const int* in_sizes, int n_in,
                              void* d_out, int out_size)
{
    const float* inp1 = (const float*)d_in[0];
    const float* inp2 = (const float*)d_in[1];
    const float* W1   = (const float*)d_in[2];
    const float* b1   = (const float*)d_in[3];
    const float* W2   = (const float*)d_in[4];
    const float* b2   = (const float*)d_in[5];
    (void)in_sizes; (void)n_in; (void)out_size;

    prep_all<<<NB_ALL, 256>>>(inp1, inp2, W1, W2);

    cudaFuncSetAttribute(fused_k1, cudaFuncAttributeMaxDynamicSharedMemorySize, SMEM_TOTAL);
    fused_k1<<<148, 512, SMEM_TOTAL>>>(inp1, inp2, b1);

    cudaFuncSetAttribute(fused_k2, cudaFuncAttributeMaxDynamicSharedMemorySize, K2_SMEM);
    fused_k2<<<dim3(N1 / BN, B_SZ / BM), 256, K2_SMEM>>>(b2, (float*)d_out);
}

// round 16
// speedup vs baseline: 1.1111x; 1.0598x over previous
#include <cuda_runtime.h>
#include <cuda_fp16.h>
#include <cstdint>
#include <cstddef>

// ---------------- problem constants ----------------
#define B_SZ   2048
#define I_SZ   256
#define P_SZ   257
#define FLATK  66049        // 257*257
#define N1     512

// ---------------- kernel-1 tiling (main part: i<256, j<256) ----------------
#define BM     128
#define BN     64
#define CSTR   264          // c_s row stride in halves
#define NSTR   72           // B tile n stride in halves
#define NSTG   4            // stages per igl (each stage = 64 j = 2 old kt)
#define NIG_G  64           // i-groups per warp-group
#define BS_HALVES (128*NSTR)              // one B buffer: 128 k-rows (2i x 64j) x 72
#define SMEM_C_BYTES (BM*CSTR*2)          // 67584
#define SMEM_TOTAL   (SMEM_C_BYTES + 6*BS_HALVES*2)  // 67584 + 110592 = 178176

// ---------------- k2/border tiling ----------------
#define K2_ABUF  18432
#define K2_BBUF  9216
#define K2_BUF   (K2_ABUF + K2_BBUF)
#define K2_SMEM  (3 * K2_BUF)             // 82944

#define AB_K     576        // border K padded: 513 -> 9*64
#define NWORK    20         // border worker CTAs (148 - 128)

// prep_all block partition
#define NB_W1   16513
#define NB_W2   128
#define NB_A    1152
#define NB_ALL  (NB_W1 + NB_W2 + NB_A)    // 17793

// statics
__device__ __half g_W1h[(size_t)FLATK * N1];
__device__ __half g_W2h[(size_t)N1 * N1];
__device__ __half g_Hh[(size_t)B_SZ * N1];
__device__ __half g_Ab[(size_t)B_SZ * AB_K];
__device__ float  g_Bord[(size_t)B_SZ * N1];
__device__ int    g_done[128];     // border tile flags

__device__ __forceinline__ void mma16(float* d, uint32_t a0, uint32_t a1,
                                      uint32_t a2, uint32_t a3,
                                      uint32_t b0, uint32_t b1) {
    asm volatile(
        "mma.sync.aligned.m16n8k16.row.col.f32.f16.f16.f32 "
        "{%0,%1,%2,%3}, {%4,%5,%6,%7}, {%8,%9}, {%0,%1,%2,%3};"
        : "+f"(d[0]), "+f"(d[1]), "+f"(d[2]), "+f"(d[3])
        : "r"(a0), "r"(a1), "r"(a2), "r"(a3), "r"(b0), "r"(b1));
}
__device__ __forceinline__ uint32_t smem_u32(const void* p) {
    uint32_t a;
    asm("{ .reg .u64 t; cvta.to.shared.u64 t, %1; cvt.u32.u64 %0, t; }" : "=r"(a) : "l"(p));
    return a;
}
__device__ __forceinline__ void ldm_x4(uint32_t& r0, uint32_t& r1, uint32_t& r2,
                                       uint32_t& r3, uint32_t a) {
    asm volatile("ldmatrix.sync.aligned.m8n8.x4.shared.b16 {%0,%1,%2,%3}, [%4];"
                 : "=r"(r0), "=r"(r1), "=r"(r2), "=r"(r3) : "r"(a));
}
__device__ __forceinline__ void ldm_x4t(uint32_t& r0, uint32_t& r1, uint32_t& r2,
                                        uint32_t& r3, uint32_t a) {
    asm volatile("ldmatrix.sync.aligned.m8n8.x4.trans.shared.b16 {%0,%1,%2,%3}, [%4];"
                 : "=r"(r0), "=r"(r1), "=r"(r2), "=r"(r3) : "r"(a));
}
__device__ __forceinline__ void cpa16(uint32_t s, const void* g) {
    asm volatile("cp.async.cg.shared.global [%0], [%1], 16;" :: "r"(s), "l"(g));
}
__device__ __forceinline__ void cpcommit() { asm volatile("cp.async.commit_group;"); }
__device__ __forceinline__ void cpwait1()  { asm volatile("cp.async.wait_group 1;"); }
__device__ __forceinline__ void bar_named(int id) {
    asm volatile("bar.sync %0, 256;" :: "r"(id) : "memory");
}
// release publish / acquire consume (gpu scope)
__device__ __forceinline__ void flag_set(int* p) {
    asm volatile("st.global.release.gpu.s32 [%0], 1;" :: "l"(p) : "memory");
}
__device__ __forceinline__ int flag_get(const int* p) {
    int v;
    asm volatile("ld.global.acquire.gpu.s32 %0, [%1];" : "=r"(v) : "l"(p) : "memory");
    return v;
}

__device__ __forceinline__ uint4 cvt8_f32_to_h16(float4 v0, float4 v1) {
    __half2 h0 = __floats2half2_rn(v0.x, v0.y);
    __half2 h1 = __floats2half2_rn(v0.z, v0.w);
    __half2 h2 = __floats2half2_rn(v1.x, v1.y);
    __half2 h3 = __floats2half2_rn(v1.z, v1.w);
    uint4 u;
    u.x = *(uint32_t*)&h0; u.y = *(uint32_t*)&h1;
    u.z = *(uint32_t*)&h2; u.w = *(uint32_t*)&h3;
    return u;
}

// ---------------------------------------------------------------------------
// prep_all: convW1 + convW2 + convA + flag reset in ONE launch.
// ---------------------------------------------------------------------------
__global__ void __launch_bounds__(256)
prep_all(const float* __restrict__ inp1, const float* __restrict__ inp2,
         const float* __restrict__ W1, const float* __restrict__ W2)
{
    const int bid = blockIdx.x, tid = threadIdx.x;

    if (bid == 0 && tid < 128) g_done[tid] = 0;

    if (bid < NB_W1) {
        const size_t total = (size_t)FLATK * N1;
        size_t idx = ((size_t)bid * 256 + tid) * 8;
        if (idx >= total) return;
        float4 v0 = *(const float4*)(W1 + idx);
        float4 v1 = *(const float4*)(W1 + idx + 4);
        *(uint4*)(g_W1h + idx) = cvt8_f32_to_h16(v0, v1);
        return;
    }

    if (bid < NB_W1 + NB_W2) {
        size_t idx = ((size_t)(bid - NB_W1) * 256 + tid) * 8;
        float4 v0 = *(const float4*)(W2 + idx);
        float4 v1 = *(const float4*)(W2 + idx + 4);
        *(uint4*)(g_W2h + idx) = cvt8_f32_to_h16(v0, v1);
        return;
    }

    // convA
    int t = (bid - NB_W1 - NB_W2) * 256 + tid;
    int m = t / (AB_K / 4);
    int c4 = (t - m * (AB_K / 4)) * 4;
    __half h[4];
    #pragma unroll
    for (int e = 0; e < 4; ++e) {
        int col = c4 + e;
        float v;
        if (col < I_SZ)       v = inp2[(size_t)m * I_SZ + col];
        else if (col == I_SZ) v = 1.0f;
        else if (col < 513)   v = inp1[(size_t)m * I_SZ + (col - 257)];
        else                  v = 0.0f;
        h[e] = __float2half_rn(v);
    }
    uint2 u2;
    u2.x = *(uint32_t*)&h[0];
    u2.y = *(uint32_t*)&h[2];
    *(uint2*)&g_Ab[(size_t)m * AB_K + c4] = u2;
}

// ---------------------------------------------------------------------------
// Fused kernel 1: 148 CTAs, all wave-1 co-resident (smem forces 1 CTA/SM).
//   bid <  128 : main GEMM (i<256, j<256), 512 thr, 2 warp-groups, BK=64
//   bid >= 128 : border worker — g_Bord = [cext|a] @ Wb + b1, per-tile flags.
// ---------------------------------------------------------------------------
extern __shared__ char smem1[];

__global__ void __launch_bounds__(512, 1)
fused_k1(const float* __restrict__ inp1, const float* __restrict__ inp2,
         const float* __restrict__ b1)
{
    const int bid  = blockIdx.x;
    const int tid  = threadIdx.x;
    const int lane = tid & 31;
    const int wid  = tid >> 5;
    const int gq   = lane >> 2;
    const int tig  = lane & 3;

    const int quad = lane >> 3, lrow = lane & 7;
    const int lmr  = (quad & 1) * 8 + lrow;
    const int lmc  = (quad >> 1) * 8;

    // =======================================================================
    // BORDER WORKER PATH (unchanged)
    // =======================================================================
    if (bid >= 128) {
        if (wid >= 8) return;          // warps 0..7 only (256 threads)
        const int worker = bid - 128;
        const int wm = wid & 3;
        const int wn = wid >> 2;
        const uint32_t sbase = smem_u32(smem1);

        for (int t = worker; t < 128; t += NWORK) {
            const int n0 = (t & 7) * BN;
            const int m0 = (t >> 3) * BM;

            auto issue = [&](int s, int buf) {
                const int k0 = s * 64;
                const uint32_t abase = sbase + (uint32_t)(buf * K2_BUF);
                #pragma unroll
                for (int q = 0; q < 4; ++q) {
                    int ch  = tid + q * 256;
                    int row = ch >> 3;
                    int c16 = ch & 7;
                    const __half* src = g_Ab + (size_t)(m0 + row) * AB_K + k0 + c16 * 8;
                    cpa16(abase + (uint32_t)(row * 144 + c16 * 16), src);
                }
                const uint32_t bbase = abase + K2_ABUF;
                #pragma unroll
                for (int q = 0; q < 2; ++q) {
                    int ch  = tid + q * 256;
                    int row = ch >> 3;
                    int c16 = ch & 7;
                    int kk  = k0 + row;
                    int grow;
                    if (kk < 257)      grow = 65792 + kk;
                    else if (kk < 513) grow = (kk - 257) * P_SZ + 256;
                    else               grow = 0;
                    const __half* src = g_W1h + (size_t)grow * N1 + n0 + c16 * 8;
                    cpa16(bbase + (uint32_t)(row * 144 + c16 * 16), src);
                }
            };

            float acc[2][4][4];
            #pragma unroll
            for (int mt = 0; mt < 2; ++mt)
                #pragma unroll
                for (int nt = 0; nt < 4; ++nt)
                    #pragma unroll
                    for (int r = 0; r < 4; ++r) acc[mt][nt][r] = 0.0f;

            issue(0, 0); cpcommit();
            issue(1, 1); cpcommit();

            int bufR = 0, bufW = 2;
            const int NST = AB_K / 64;   // 9

            for (int s = 0; s < NST; ++s) {
                cpwait1();
                bar_named(3);
                if (s + 2 < NST) issue(s + 2, bufW);
                cpcommit();

                const uint32_t abase = sbase + (uint32_t)(bufR * K2_BUF);
                const uint32_t bbase = abase + K2_ABUF;

                #pragma unroll
                for (int ks = 0; ks < 4; ++ks) {
                    uint32_t A[2][4];
                    #pragma unroll
                    for (int mt = 0; mt < 2; ++mt) {
                        uint32_t addr = abase + (uint32_t)(
                            (wm * 32 + mt * 16 + lmr) * 144 + (ks * 16 + lmc) * 2);
                        ldm_x4(A[mt][0], A[mt][1], A[mt][2], A[mt][3], addr);
                    }
                    #pragma unroll
                    for (int nh = 0; nh < 2; ++nh) {
                        uint32_t addr = bbase + (uint32_t)(
                            (ks * 16 + lmr) * 144 + (wn * 32 + nh * 16 + lmc) * 2);
                        uint32_t b0, b1r, b2r, b3;
                        ldm_x4t(b0, b1r, b2r, b3, addr);
                        #pragma unroll
                        for (int mt = 0; mt < 2; ++mt) {
                            mma16(acc[mt][nh * 2 + 0], A[mt][0], A[mt][1], A[mt][2], A[mt][3], b0, b1r);
                            mma16(acc[mt][nh * 2 + 1], A[mt][0], A[mt][1], A[mt][2], A[mt][3], b2r, b3);
                        }
                    }
                }
                bufR = (bufR == 2) ? 0 : bufR + 1;
                bufW = (bufW == 2) ? 0 : bufW + 1;
            }

            #pragma unroll
            for (int mt = 0; mt < 2; ++mt)
                #pragma unroll
                for (int nt = 0; nt < 4; ++nt) {
                    int n_base = n0 + wn * 32 + nt * 8 + tig * 2;
                    float bv0 = b1[n_base], bv1 = b1[n_base + 1];
                    #pragma unroll
                    for (int h = 0; h < 2; ++h) {
                        int m = m0 + wm * 32 + mt * 16 + h * 8 + gq;
                        *(float2*)&g_Bord[(size_t)m * N1 + n_base] =
                            make_float2(acc[mt][nt][h * 2 + 0] + bv0,
                                        acc[mt][nt][h * 2 + 1] + bv1);
                    }
                }

            bar_named(3);
            if (tid == 0) flag_set(&g_done[t]);
            bar_named(3);
        }
        return;
    }

    // =======================================================================
    // MAIN PATH (128 CTAs) — BK=64 per stage, 2 half-steps per barrier
    // =======================================================================
    const int grp  = wid >> 3;
    const int gtid = tid & 255;
    const int gwid = wid & 7;
    const int wm   = gwid & 3;
    const int wn   = gwid >> 2;
    const int n0   = (bid & 7) * BN;
    const int m0   = (bid >> 3) * BM;

    __half* c_s = (__half*)smem1;
    __half* b_s = (__half*)(smem1 + SMEM_C_BYTES);

    const int igbase = grp * NIG_G;
    const uint32_t c_base  = smem_u32(c_s);
    const uint32_t bring_u = smem_u32(b_s) + (uint32_t)(grp * 3 * BS_HALVES * 2);

    for (int idx = tid; idx < BM * 256; idx += 512) {
        int m = idx >> 8, j = idx & 255;
        c_s[m * CSTR + j] = __float2half_rn(inp2[(size_t)(m0 + m) * I_SZ + j]);
    }
    __syncthreads();

    // stage = (igl, st): B tile = 128 rows (2 i's x 64 j), j0 = st*64
    auto issueW = [&](int igl, int st, int buf) {
        int ig = igbase + igl;
        #pragma unroll
        for (int q = 0; q < 4; ++q) {
            int ch  = gtid + q * 256;        // 0..1023 16B chunks
            int row = ch >> 3;               // 0..127: g*64 + jlocal
            int c16 = ch & 7;
            int i   = ig * 2 + (row >> 6);
            int grow = i * P_SZ + st * 64 + (row & 63);
            const __half* src = g_W1h + (size_t)grow * N1 + n0 + c16 * 8;
            uint32_t dst = bring_u + (uint32_t)(buf * BS_HALVES * 2 + row * 144 + c16 * 16);
            cpa16(dst, src);
        }
    };

    float h_acc[2][4][4];
    #pragma unroll
    for (int mt = 0; mt < 2; ++mt)
        #pragma unroll
        for (int nt = 0; nt < 4; ++nt)
            #pragma unroll
            for (int r = 0; r < 4; ++r) h_acc[mt][nt][r] = 0.0f;

    issueW(0, 0, 0); cpcommit();
    issueW(0, 1, 1); cpcommit();

    int bufR = 0, bufW = 2;

    for (int igl = 0; igl < NIG_G; ++igl) {
        float av[2][4];
        #pragma unroll
        for (int g = 0; g < 2; ++g) {
            int i = (igbase + igl) * 2 + g;
            #pragma unroll
            for (int q = 0; q < 4; ++q) {
                int m = m0 + wm * 32 + (q >> 1) * 16 + (q & 1) * 8 + gq;
                av[g][q] = __ldg(&inp1[(size_t)m * I_SZ + i]);
            }
        }

        float tmp[2][2][4][4];
        #pragma unroll
        for (int g = 0; g < 2; ++g)
            #pragma unroll
            for (int mt = 0; mt < 2; ++mt)
                #pragma unroll
                for (int nt = 0; nt < 4; ++nt)
                    #pragma unroll
                    for (int q = 0; q < 4; ++q) tmp[g][mt][nt][q] = 0.0f;

        for (int st = 0; st < NSTG; ++st) {
            const int j0 = st * 64;

            // A fragments for half-step 0 (c_s immutable — before barrier)
            uint32_t A[2][2][4];
            #pragma unroll
            for (int ks = 0; ks < 2; ++ks)
                #pragma unroll
                for (int mt = 0; mt < 2; ++mt) {
                    uint32_t addr = c_base + 2u * (uint32_t)(
                        (wm * 32 + mt * 16 + lmr) * CSTR + j0 + ks * 16 + lmc);
                    ldm_x4(A[ks][mt][0], A[ks][mt][1], A[ks][mt][2], A[ks][mt][3], addr);
                }

            cpwait1();
            bar_named(grp + 1);        // ONE barrier per 64-j stage

            const uint32_t bb = bring_u + (uint32_t)(bufR * BS_HALVES * 2);

            #pragma unroll
            for (int kh = 0; kh < 2; ++kh) {
                if (kh == 1) {
                    // reload A fragments for half-step 1
                    #pragma unroll
                    for (int ks = 0; ks < 2; ++ks)
                        #pragma unroll
                        for (int mt = 0; mt < 2; ++mt) {
                            uint32_t addr = c_base + 2u * (uint32_t)(
                                (wm * 32 + mt * 16 + lmr) * CSTR + j0 + 32 + ks * 16 + lmc);
                            ldm_x4(A[ks][mt][0], A[ks][mt][1], A[ks][mt][2], A[ks][mt][3], addr);
                        }
                }
                #pragma unroll
                for (int g = 0; g < 2; ++g) {
                    #pragma unroll
                    for (int ks = 0; ks < 2; ++ks) {
                        #pragma unroll
                        for (int nh = 0; nh < 2; ++nh) {
                            uint32_t addr = bb + 2u * (uint32_t)(
                                (g * 64 + kh * 32 + ks * 16 + lmr) * NSTR
                                + wn * 32 + nh * 16 + lmc);
                            uint32_t b0, b1r, b2r, b3;
                            ldm_x4t(b0, b1r, b2r, b3, addr);
                            #pragma unroll
                            for (int mt = 0; mt < 2; ++mt) {
                                mma16(tmp[g][mt][nh * 2 + 0],
                                      A[ks][mt][0], A[ks][mt][1], A[ks][mt][2], A[ks][mt][3],
                                      b0, b1r);
                                mma16(tmp[g][mt][nh * 2 + 1],
                                      A[ks][mt][0], A[ks][mt][1], A[ks][mt][2], A[ks][mt][3],
                                      b2r, b3);
                            }
                        }
                    }
                }
            }

            // prefetch stage r+2
            int st2 = st + 2, ig2 = igl;
            if (st2 >= NSTG) { st2 -= NSTG; ++ig2; }
            if (ig2 < NIG_G) issueW(ig2, st2, bufW);
            cpcommit();

            bufR = (bufR == 2) ? 0 : bufR + 1;
            bufW = (bufW == 2) ? 0 : bufW + 1;
        }

        #pragma unroll
        for (int g = 0; g < 2; ++g)
            #pragma unroll
            for (int mt = 0; mt < 2; ++mt)
                #pragma unroll
                for (int nt = 0; nt < 4; ++nt)
                    #pragma unroll
                    for (int q = 0; q < 4; ++q)
                        h_acc[mt][nt][q] += av[g][mt * 2 + (q >> 1)] * tmp[g][mt][nt][q];
    }

    // ---- wait for this tile's border partial (producers co-resident) ----
    if (tid == 0) {
        while (flag_get(&g_done[bid]) == 0) { __nanosleep(64); }
    }
    __syncthreads();

    // ---- cross-group reduce through retired c_s region ----
    float* xbuf = (float*)smem1;
    if (grp == 1) {
        #pragma unroll
        for (int mt = 0; mt < 2; ++mt)
            #pragma unroll
            for (int nt = 0; nt < 4; ++nt)
                *(float4*)&xbuf[gtid * 36 + (mt * 4 + nt) * 4] =
                    make_float4(h_acc[mt][nt][0], h_acc[mt][nt][1],
                                h_acc[mt][nt][2], h_acc[mt][nt][3]);
    }
    __syncthreads();
    if (grp == 0) {
        #pragma unroll
        for (int mt = 0; mt < 2; ++mt)
            #pragma unroll
            for (int nt = 0; nt < 4; ++nt) {
                float4 p = *(const float4*)&xbuf[gtid * 36 + (mt * 4 + nt) * 4];
                h_acc[mt][nt][0] += p.x; h_acc[mt][nt][1] += p.y;
                h_acc[mt][nt][2] += p.z; h_acc[mt][nt][3] += p.w;

                int n_base = n0 + wn * 32 + nt * 8 + tig * 2;
                #pragma unroll
                for (int h = 0; h < 2; ++h) {
                    int m = m0 + wm * 32 + mt * 16 + h * 8 + gq;
                    const float2* bp = (const float2*)&g_Bord[(size_t)m * N1 + n_base];
                    float2 bo;
                    bo.x = __ldcg(&bp->x);
                    bo.y = __ldcg(&bp->y);
                    float v0 = fmaxf(h_acc[mt][nt][h * 2 + 0] + bo.x, 0.0f);
                    float v1 = fmaxf(h_acc[mt][nt][h * 2 + 1] + bo.y, 0.0f);
                    __half2 hv = __floats2half2_rn(v0, v1);
                    *(__half2*)&g_Hh[(size_t)m * N1 + n_base] = hv;
                }
            }
    }
}

// ---------------------------------------------------------------------------
// Kernel 2: out = relu( H @ W2 + b2 ) — fp16 tensor-core, fp32 accum.
// ---------------------------------------------------------------------------
extern __shared__ char smem2[];

__global__ void __launch_bounds__(256, 1)
fused_k2(const float* __restrict__ b2, float* __restrict__ out)
{
    const int tid  = threadIdx.x;
    const int lane = tid & 31;
    const int wid  = tid >> 5;
    const int wm   = wid & 3;
    const int wn   = wid >> 2;
    const int gq   = lane >> 2;
    const int tig  = lane & 3;
    const int m0   = blockIdx.y * BM;
    const int n0   = blockIdx.x * BN;

    const uint32_t sbase = smem_u32(smem2);
    const int quad = lane >> 3, lrow = lane & 7;
    const int lmr  = (quad & 1) * 8 + lrow;
    const int lmc  = (quad >> 1) * 8;

    auto issue = [&](int s, int buf) {
        const int k0 = s * 64;
        const uint32_t abase = sbase + (uint32_t)(buf * K2_BUF);
        #pragma unroll
        for (int q = 0; q < 4; ++q) {
            int ch  = tid + q * 256;
            int row = ch >> 3;
            int c16 = ch & 7;
            const __half* src = g_Hh + (size_t)(m0 + row) * N1 + k0 + c16 * 8;
            cpa16(abase + (uint32_t)(row * 144 + c16 * 16), src);
        }
        const uint32_t bbase = abase + K2_ABUF;
        #pragma unroll
        for (int q = 0; q < 2; ++q) {
            int ch  = tid + q * 256;
            int row = ch >> 3;
            int c16 = ch & 7;
            const __half* src = g_W2h + (size_t)(k0 + row) * N1 + n0 + c16 * 8;
            cpa16(bbase + (uint32_t)(row * 144 + c16 * 16), src);
        }
    };

    float acc[2][4][4];
    #pragma unroll
    for (int mt = 0; mt < 2; ++mt)
        #pragma unroll
        for (int nt = 0; nt < 4; ++nt)
            #pragma unroll
            for (int r = 0; r < 4; ++r) acc[mt][nt][r] = 0.0f;

    issue(0, 0); cpcommit();
    issue(1, 1); cpcommit();

    int bufR = 0, bufW = 2;
    const int NST = N1 / 64;

    for (int s = 0; s < NST; ++s) {
        cpwait1();
        __syncthreads();
        if (s + 2 < NST) issue(s + 2, bufW);
        cpcommit();

        const uint32_t abase = sbase + (uint32_t)(bufR * K2_BUF);
        const uint32_t bbase = abase + K2_ABUF;

        #pragma unroll
        for (int ks = 0; ks < 4; ++ks) {
            uint32_t A[2][4];
            #pragma unroll
            for (int mt = 0; mt < 2; ++mt) {
                uint32_t addr = abase + (uint32_t)(
                    (wm * 32 + mt * 16 + lmr) * 144 + (ks * 16 + lmc) * 2);
                ldm_x4(A[mt][0], A[mt][1], A[mt][2], A[mt][3], addr);
            }
            #pragma unroll
            for (int nh = 0; nh < 2; ++nh) {
                uint32_t addr = bbase + (uint32_t)(
                    (ks * 16 + lmr) * 144 + (wn * 32 + nh * 16 + lmc) * 2);
                uint32_t b0, b1, b2, b3;
                ldm_x4t(b0, b1, b2, b3, addr);
                #pragma unroll
                for (int mt = 0; mt < 2; ++mt) {
                    mma16(acc[mt][nh * 2 + 0], A[mt][0], A[mt][1], A[mt][2], A[mt][3], b0, b1);
                    mma16(acc[mt][nh * 2 + 1], A[mt][0], A[mt][1], A[mt][2], A[mt][3], b2, b3);
                }
            }
        }
        bufR = (bufR == 2) ? 0 : bufR + 1;
        bufW = (bufW == 2) ? 0 : bufW + 1;
    }

    #pragma unroll
    for (int mt = 0; mt < 2; ++mt)
        #pragma unroll
        for (int nt = 0; nt < 4; ++nt) {
            int n_base = n0 + wn * 32 + nt * 8 + tig * 2;
            float bv0 = b2[n_base], bv1 = b2[n_base + 1];
            #pragma unroll
            for (int h = 0; h < 2; ++h) {
                int m = m0 + wm * 32 + mt * 16 + h * 8 + gq;
                float v0 = fmaxf(acc[mt][nt][h * 2 + 0] + bv0, 0.0f);
                float v1 = fmaxf(acc[mt][nt][h * 2 + 1] + bv1, 0.0f);
                *(float2*)&out[(size_t)m * N1 + n_base] = make_float2(v0, v1);
            }
        }
}

// ---------------------------------------------------------------------------
extern "C" void kernel_launch(void* const* d_in, const int* in_sizes, int n_in,
                              void* d_out, int out_size)
{
    const float* inp1 = (const float*)d_in[0];
    const float* inp2 = (const float*)d_in[1];
    const float* W1   = (const float*)d_in[2];
    const float* b1   = (const float*)d_in[3];
    const float* W2   = (const float*)d_in[4];
    const float* b2   = (const float*)d_in[5];
    (void)in_sizes; (void)n_in; (void)out_size;

    prep_all<<<NB_ALL, 256>>>(inp1, inp2, W1, W2);

    cudaFuncSetAttribute(fused_k1, cudaFuncAttributeMaxDynamicSharedMemorySize, SMEM_TOTAL);
    fused_k1<<<148, 512, SMEM_TOTAL>>>(inp1, inp2, b1);

    cudaFuncSetAttribute(fused_k2, cudaFuncAttributeMaxDynamicSharedMemorySize, K2_SMEM);
    fused_k2<<<dim3(N1 / BN, B_SZ / BM), 256, K2_SMEM>>>(b2, (float*)d_out);
}